// round 4
// baseline (speedup 1.0000x reference)
#include <cuda_runtime.h>
#include <cuda_bf16.h>

// RCNNTargetGenerator: elementwise over N boxes.
// out layout (float32, 12N elems): [targets 4N | inside_w 4N | outside_w 4N]
// Each thread handles 4 boxes -> all global accesses are aligned 128-bit.

__global__ __launch_bounds__(256)
void rcnn_target_kernel(const float* __restrict__ gt,     // [N,5] (x1,y1,x2,y2,cls)
                        const float* __restrict__ roi,    // [N,5] (b,x1,y1,x2,y2)
                        const int*   __restrict__ labels, // [N]
                        const float* __restrict__ means,  // [4]
                        const float* __restrict__ stds,   // [4]
                        const float* __restrict__ inw,    // [4]
                        float* __restrict__ out, int n)
{
    int t = blockIdx.x * blockDim.x + threadIdx.x;
    long base = (long)t * 4;
    if (base >= n) return;

    float4 mv = __ldg((const float4*)means);
    float4 sv = __ldg((const float4*)stds);
    float4 wv = __ldg((const float4*)inw);
    float m[4]  = {mv.x, mv.y, mv.z, mv.w};
    float is[4] = {__fdividef(1.0f, sv.x), __fdividef(1.0f, sv.y),
                   __fdividef(1.0f, sv.z), __fdividef(1.0f, sv.w)};
    float w[4]  = {wv.x, wv.y, wv.z, wv.w};

    float4* out_t  = (float4*)out;
    float4* out_iw = (float4*)(out + (size_t)4 * n);
    float4* out_ow = (float4*)(out + (size_t)8 * n);

    if (base + 4 <= n) {
        // ---- fast path: 4 boxes, fully vectorized ----
        float gf[20], rf[20];
        const float4* g4 = (const float4*)gt  + (size_t)t * 5;
        const float4* r4 = (const float4*)roi + (size_t)t * 5;
#pragma unroll
        for (int k = 0; k < 5; k++) {
            ((float4*)gf)[k] = __ldg(g4 + k);
            ((float4*)rf)[k] = __ldg(r4 + k);
        }
        int4 lab4 = __ldg((const int4*)labels + t);
        int lab[4] = {lab4.x, lab4.y, lab4.z, lab4.w};

#pragma unroll
        for (int j = 0; j < 4; j++) {
            const float* G = gf + j * 5;   // gt box: cols 0..3
            const float* R = rf + j * 5;   // roi box: cols 1..4

            float ex_w  = R[3] - R[1] + 1.0f;
            float ex_h  = R[4] - R[2] + 1.0f;
            float ex_cx = R[1] + 0.5f * ex_w;
            float ex_cy = R[2] + 0.5f * ex_h;
            float gt_w  = G[2] - G[0] + 1.0f;
            float gt_h  = G[3] - G[1] + 1.0f;
            float gt_cx = G[0] + 0.5f * gt_w;
            float gt_cy = G[1] + 0.5f * gt_h;

            float dx = __fdividef(gt_cx - ex_cx, ex_w);
            float dy = __fdividef(gt_cy - ex_cy, ex_h);
            float dw = __logf(__fdividef(gt_w, ex_w));
            float dh = __logf(__fdividef(gt_h, ex_h));

            bool pos = lab[j] > 0;
            float4 tg, iw, ow;
            tg.x = pos ? (dx - m[0]) * is[0] : 0.0f;
            tg.y = pos ? (dy - m[1]) * is[1] : 0.0f;
            tg.z = pos ? (dw - m[2]) * is[2] : 0.0f;
            tg.w = pos ? (dh - m[3]) * is[3] : 0.0f;
            iw.x = pos ? w[0] : 0.0f;
            iw.y = pos ? w[1] : 0.0f;
            iw.z = pos ? w[2] : 0.0f;
            iw.w = pos ? w[3] : 0.0f;
            ow.x = (iw.x > 0.0f) ? 1.0f : 0.0f;
            ow.y = (iw.y > 0.0f) ? 1.0f : 0.0f;
            ow.z = (iw.z > 0.0f) ? 1.0f : 0.0f;
            ow.w = (iw.w > 0.0f) ? 1.0f : 0.0f;

            out_t [base + j] = tg;
            out_iw[base + j] = iw;
            out_ow[base + j] = ow;
        }
    } else {
        // ---- scalar tail (n % 4 != 0) ----
        for (long i = base; i < n; i++) {
            const float* G = gt  + i * 5;
            const float* R = roi + i * 5;
            float ex_w  = R[3] - R[1] + 1.0f;
            float ex_h  = R[4] - R[2] + 1.0f;
            float ex_cx = R[1] + 0.5f * ex_w;
            float ex_cy = R[2] + 0.5f * ex_h;
            float gt_w  = G[2] - G[0] + 1.0f;
            float gt_h  = G[3] - G[1] + 1.0f;
            float gt_cx = G[0] + 0.5f * gt_w;
            float gt_cy = G[1] + 0.5f * gt_h;

            float d[4];
            d[0] = __fdividef(gt_cx - ex_cx, ex_w);
            d[1] = __fdividef(gt_cy - ex_cy, ex_h);
            d[2] = __logf(__fdividef(gt_w, ex_w));
            d[3] = __logf(__fdividef(gt_h, ex_h));

            bool pos = labels[i] > 0;
#pragma unroll
            for (int c = 0; c < 4; c++) {
                float tg = pos ? (d[c] - m[c]) * is[c] : 0.0f;
                float iw = pos ? w[c] : 0.0f;
                out[(size_t)i * 4 + c]         = tg;
                out[(size_t)4 * n + i * 4 + c] = iw;
                out[(size_t)8 * n + i * 4 + c] = (iw > 0.0f) ? 1.0f : 0.0f;
            }
        }
    }
}

extern "C" void kernel_launch(void* const* d_in, const int* in_sizes, int n_in,
                              void* d_out, int out_size)
{
    const float* gt     = (const float*)d_in[0];  // gt_rois [1,N,5]
    const float* roi    = (const float*)d_in[1];  // rois    [1,N,5]
    const int*   labels = (const int*)  d_in[2];  // labels  [N] (int32 after JAX canonicalization)
    const float* means  = (const float*)d_in[3];
    const float* stds   = (const float*)d_in[4];
    const float* inw    = (const float*)d_in[5];
    float* out = (float*)d_out;

    int n = in_sizes[0] / 5;
    int nthreads = (n + 3) / 4;
    int blocks = (nthreads + 255) / 256;
    rcnn_target_kernel<<<blocks, 256>>>(gt, roi, labels, means, stds, inw, out, n);
}

// round 12
// speedup vs baseline: 1.4468x; 1.4468x over previous
#include <cuda_runtime.h>
#include <cuda_bf16.h>

// RCNNTargetGenerator: elementwise over N boxes.
// out layout (float32, 12N elems): [targets 4N | inside_w 4N | outside_w 4N]
//
// Strategy: stride-5 AoS rows are staged through shared memory with fully
// coalesced float4 loads (fixes 5x L1tex wavefront inflation of the direct
// per-thread float4 approach). 1 box/thread makes all stores minimally
// coalesced (4 wavefronts per STG.128).

#define TPB 256

__global__ __launch_bounds__(TPB)
void rcnn_target_kernel(const float* __restrict__ gt,     // [N,5] (x1,y1,x2,y2,cls)
                        const float* __restrict__ roi,    // [N,5] (b,x1,y1,x2,y2)
                        const int*   __restrict__ labels, // [N]
                        const float* __restrict__ means,  // [4]
                        const float* __restrict__ stds,   // [4]
                        const float* __restrict__ inw,    // [4]
                        float* __restrict__ out, int n)
{
    __shared__ float gs[TPB * 5];
    __shared__ float rs[TPB * 5];

    const int  tid = threadIdx.x;
    const long b0  = (long)blockIdx.x * TPB;      // first box of this block
    const long f0  = b0 * 5;                      // first float of this block
    const int  cnt = (int)min((long)TPB, (long)n - b0);  // boxes handled here
    const int  nfl = cnt * 5;                     // floats to stage

    // ---- cooperative coalesced load: global AoS -> smem ----
    // f0 = blockIdx.x * 1280 floats -> 16B aligned.
    {
        const float4* g4 = (const float4*)(gt  + f0);
        const float4* r4 = (const float4*)(roi + f0);
        const int nv = nfl >> 2;                  // whole float4s
        for (int i = tid; i < nv; i += TPB) {
            ((float4*)gs)[i] = __ldg(g4 + i);
            ((float4*)rs)[i] = __ldg(r4 + i);
        }
        for (int i = (nv << 2) + tid; i < nfl; i += TPB) {  // ragged tail floats
            gs[i] = __ldg(gt  + f0 + i);
            rs[i] = __ldg(roi + f0 + i);
        }
    }
    __syncthreads();

    if (tid >= cnt) return;

    const long i = b0 + tid;

    // uniform params (L1-broadcast, negligible)
    const float4 mv = __ldg((const float4*)means);
    const float4 sv = __ldg((const float4*)stds);
    const float4 wv = __ldg((const float4*)inw);

    // smem reads: stride-5 word addresses, 5 coprime 32 -> conflict-free
    const float* G = gs + tid * 5;   // gt box: cols 0..3
    const float* R = rs + tid * 5;   // roi box: cols 1..4

    float ex_w  = R[3] - R[1] + 1.0f;
    float ex_h  = R[4] - R[2] + 1.0f;
    float ex_cx = R[1] + 0.5f * ex_w;
    float ex_cy = R[2] + 0.5f * ex_h;
    float gt_w  = G[2] - G[0] + 1.0f;
    float gt_h  = G[3] - G[1] + 1.0f;
    float gt_cx = G[0] + 0.5f * gt_w;
    float gt_cy = G[1] + 0.5f * gt_h;

    float dx = __fdividef(gt_cx - ex_cx, ex_w);
    float dy = __fdividef(gt_cy - ex_cy, ex_h);
    float dw = __logf(__fdividef(gt_w, ex_w));
    float dh = __logf(__fdividef(gt_h, ex_h));

    const bool pos = __ldg(labels + i) > 0;

    float4 tg, iw, ow;
    tg.x = pos ? __fdividef(dx - mv.x, sv.x) : 0.0f;
    tg.y = pos ? __fdividef(dy - mv.y, sv.y) : 0.0f;
    tg.z = pos ? __fdividef(dw - mv.z, sv.z) : 0.0f;
    tg.w = pos ? __fdividef(dh - mv.w, sv.w) : 0.0f;
    iw.x = pos ? wv.x : 0.0f;
    iw.y = pos ? wv.y : 0.0f;
    iw.z = pos ? wv.z : 0.0f;
    iw.w = pos ? wv.w : 0.0f;
    ow.x = (iw.x > 0.0f) ? 1.0f : 0.0f;
    ow.y = (iw.y > 0.0f) ? 1.0f : 0.0f;
    ow.z = (iw.z > 0.0f) ? 1.0f : 0.0f;
    ow.w = (iw.w > 0.0f) ? 1.0f : 0.0f;

    // lane-consecutive float4 stores: minimally coalesced
    ((float4*)out)[i]                     = tg;
    ((float4*)(out + (size_t)4 * n))[i]   = iw;
    ((float4*)(out + (size_t)8 * n))[i]   = ow;
}

extern "C" void kernel_launch(void* const* d_in, const int* in_sizes, int n_in,
                              void* d_out, int out_size)
{
    const float* gt     = (const float*)d_in[0];  // gt_rois [1,N,5]
    const float* roi    = (const float*)d_in[1];  // rois    [1,N,5]
    const int*   labels = (const int*)  d_in[2];  // labels  [N] (int32)
    const float* means  = (const float*)d_in[3];
    const float* stds   = (const float*)d_in[4];
    const float* inw    = (const float*)d_in[5];
    float* out = (float*)d_out;

    int n = in_sizes[0] / 5;
    int blocks = (n + TPB - 1) / TPB;
    rcnn_target_kernel<<<blocks, TPB>>>(gt, roi, labels, means, stds, inw, out, n);
}